// round 2
// baseline (speedup 1.0000x reference)
#include <cuda_runtime.h>
#include <cuda_bf16.h>

// ROIAlign (Caffe2 style, aligned=false), avg pool, sampling_ratio=2.
// feat: [B=2, C=256, H=200, W=272] f32, rois: [N,5] f32 -> out [N,256,7,7] f32.

#define C_    256
#define H_    200
#define W_    272
#define PH_   7
#define PW_   7
#define NBIN  (PH_ * PW_)
#define SCALE 0.25f
#define CPT   4              // channels per thread
#define CGRP  (C_ / CPT)     // 64 channel groups

__global__ void roialign_kernel(const float* __restrict__ feat,
                                const float* __restrict__ rois,
                                float* __restrict__ out,
                                int total) {
    int tid = blockIdx.x * blockDim.x + threadIdx.x;
    if (tid >= total) return;

    int bin = tid % NBIN;           // pw fastest within warp -> x-coalescing
    int t   = tid / NBIN;
    int cg  = t % CGRP;
    int n   = t / CGRP;

    int pw = bin % PW_;
    int ph = bin / PW_;

    const float* r = rois + (size_t)n * 5;
    int   b  = (int)__ldg(r + 0);
    float sw = __ldg(r + 1) * SCALE;
    float sh = __ldg(r + 2) * SCALE;
    float ew = __ldg(r + 3) * SCALE;
    float eh = __ldg(r + 4) * SCALE;

    float roi_w = fmaxf(ew - sw, 1.0f);
    float roi_h = fmaxf(eh - sh, 1.0f);
    float bin_w = roi_w * (1.0f / PW_);
    float bin_h = roi_h * (1.0f / PH_);

    int   offs[16];
    float wts[16];

    // 2x2 sampling grid: sample coord = start + (p + (i+0.5)/sr) * bin
    #pragma unroll
    for (int iy = 0; iy < 2; iy++) {
        float y  = sh + ((float)ph + ((float)iy + 0.5f) * 0.5f) * bin_h;
        bool  vy = (y > -1.0f) && (y < (float)H_);
        float yc = fminf(fmaxf(y, 0.0f), (float)(H_ - 1));
        int   yl = (int)floorf(yc);
        int   yh = min(yl + 1, H_ - 1);
        float ly = yc - (float)yl;
        float hy = 1.0f - ly;
        #pragma unroll
        for (int ix = 0; ix < 2; ix++) {
            float x  = sw + ((float)pw + ((float)ix + 0.5f) * 0.5f) * bin_w;
            bool  vx = (x > -1.0f) && (x < (float)W_);
            float xc = fminf(fmaxf(x, 0.0f), (float)(W_ - 1));
            int   xl = (int)floorf(xc);
            int   xh = min(xl + 1, W_ - 1);
            float lx = xc - (float)xl;
            float hx = 1.0f - lx;

            float v = (vy && vx) ? 0.25f : 0.0f;   // 1/(sr*sr), masked
            int k = (iy * 2 + ix) * 4;
            offs[k + 0] = yl * W_ + xl;  wts[k + 0] = hy * hx * v;
            offs[k + 1] = yl * W_ + xh;  wts[k + 1] = hy * lx * v;
            offs[k + 2] = yh * W_ + xl;  wts[k + 2] = ly * hx * v;
            offs[k + 3] = yh * W_ + xh;  wts[k + 3] = ly * lx * v;
        }
    }

    const float* fbase = feat + ((size_t)b * C_ + (size_t)cg * CPT) * (H_ * W_);
    float*       obase = out  + ((size_t)n * C_ + (size_t)cg * CPT) * NBIN + bin;

    #pragma unroll
    for (int c = 0; c < CPT; c++) {
        const float* f = fbase + (size_t)c * (H_ * W_);
        float acc = 0.0f;
        #pragma unroll
        for (int k = 0; k < 16; k++) {
            acc = fmaf(wts[k], __ldg(f + offs[k]), acc);
        }
        obase[(size_t)c * NBIN] = acc;
    }
}

extern "C" void kernel_launch(void* const* d_in, const int* in_sizes, int n_in,
                              void* d_out, int out_size) {
    const float* feat = (const float*)d_in[0];
    const float* rois = (const float*)d_in[1];
    float*       out  = (float*)d_out;

    int N = in_sizes[1] / 5;
    int total = N * NBIN * CGRP;

    int threads = 256;
    int blocks  = (total + threads - 1) / threads;
    roialign_kernel<<<blocks, threads>>>(feat, rois, out, total);
}

// round 3
// speedup vs baseline: 1.0515x; 1.0515x over previous
#include <cuda_runtime.h>
#include <cuda_bf16.h>

// ROIAlign via NHWC pre-transpose.
// feat NCHW [2,256,200,272] f32 -> g_nhwc [2,200,272,256] f32 (device scratch)
// then channel-coalesced gather kernel: out [N,256,7,7] f32.

#define B_    2
#define C_    256
#define H_    200
#define W_    272
#define HW_   (H_ * W_)
#define PH_   7
#define PW_   7
#define NBIN  (PH_ * PW_)
#define SCALE 0.25f

__device__ float g_nhwc[(size_t)B_ * HW_ * C_];   // 111.4 MB scratch

// ---------------- NCHW -> NHWC transpose (per batch: [C, HW] -> [HW, C]) ---
__global__ void transpose_kernel(const float* __restrict__ in) {
    __shared__ float tile[32][33];
    int b  = blockIdx.z;
    int gs = blockIdx.x * 32;     // HW offset  (HW_ = 54400 = 32*1700, exact)
    int gc = blockIdx.y * 32;     // C offset   (C_ = 256 = 32*8, exact)
    int tx = threadIdx.x, ty = threadIdx.y;

    const float* src = in     + (size_t)b * C_ * HW_;
    float*       dst = g_nhwc + (size_t)b * HW_ * C_;

    #pragma unroll
    for (int j = 0; j < 32; j += 8)
        tile[ty + j][tx] = src[(size_t)(gc + ty + j) * HW_ + gs + tx];
    __syncthreads();
    #pragma unroll
    for (int j = 0; j < 32; j += 8)
        dst[(size_t)(gs + ty + j) * C_ + gc + tx] = tile[tx][ty + j];
}

// ---------------- main ROIAlign on NHWC ------------------------------------
// Block = one (roi n, ph). 448 threads: c4 = tid&63 (quad of channels,
// lanes contiguous -> coalesced LDG.128), pw = tid>>6.
#define SROW (C_ + 4)   // float4-aligned padded smem row stride

__global__ __launch_bounds__(448) void roialign_nhwc(const float* __restrict__ rois,
                                                     float* __restrict__ out,
                                                     int N) {
    int n   = blockIdx.x;
    int ph  = blockIdx.y;
    int tid = threadIdx.x;
    int c4  = tid & 63;
    int pw  = tid >> 6;          // 0..6

    __shared__ float s_out[PW_][SROW];

    const float* r = rois + (size_t)n * 5;
    int   b  = (int)__ldg(r + 0);
    float sw = __ldg(r + 1) * SCALE;
    float sh = __ldg(r + 2) * SCALE;
    float ew = __ldg(r + 3) * SCALE;
    float eh = __ldg(r + 4) * SCALE;

    float roi_w = fmaxf(ew - sw, 1.0f);
    float roi_h = fmaxf(eh - sh, 1.0f);
    float bin_w = roi_w * (1.0f / PW_);
    float bin_h = roi_h * (1.0f / PH_);

    int   offs[16];
    float wts[16];

    #pragma unroll
    for (int iy = 0; iy < 2; iy++) {
        float y  = sh + ((float)ph + ((float)iy + 0.5f) * 0.5f) * bin_h;
        bool  vy = (y > -1.0f) && (y < (float)H_);
        float yc = fminf(fmaxf(y, 0.0f), (float)(H_ - 1));
        int   yl = (int)floorf(yc);
        int   yh = min(yl + 1, H_ - 1);
        float ly = yc - (float)yl;
        float hy = 1.0f - ly;
        #pragma unroll
        for (int ix = 0; ix < 2; ix++) {
            float x  = sw + ((float)pw + ((float)ix + 0.5f) * 0.5f) * bin_w;
            bool  vx = (x > -1.0f) && (x < (float)W_);
            float xc = fminf(fmaxf(x, 0.0f), (float)(W_ - 1));
            int   xl = (int)floorf(xc);
            int   xh = min(xl + 1, W_ - 1);
            float lx = xc - (float)xl;
            float hx = 1.0f - lx;

            float v = (vy && vx) ? 0.25f : 0.0f;   // 1/(sr*sr), masked
            int rowl = (b * H_ + yl) * W_;
            int rowh = (b * H_ + yh) * W_;
            int k = (iy * 2 + ix) * 4;
            offs[k + 0] = (rowl + xl) * C_;  wts[k + 0] = hy * hx * v;
            offs[k + 1] = (rowl + xh) * C_;  wts[k + 1] = hy * lx * v;
            offs[k + 2] = (rowh + xl) * C_;  wts[k + 2] = ly * hx * v;
            offs[k + 3] = (rowh + xh) * C_;  wts[k + 3] = ly * lx * v;
        }
    }

    float ax = 0.f, ay = 0.f, az = 0.f, aw = 0.f;
    #pragma unroll
    for (int k = 0; k < 16; k++) {
        const float4* p = reinterpret_cast<const float4*>(g_nhwc + offs[k]) + c4;
        float4 v = __ldg(p);
        float  w = wts[k];
        ax = fmaf(w, v.x, ax);
        ay = fmaf(w, v.y, ay);
        az = fmaf(w, v.z, az);
        aw = fmaf(w, v.w, aw);
    }

    // stage [pw][c] in smem, then write out semi-coalesced per-channel rows
    float4* srow = reinterpret_cast<float4*>(&s_out[pw][0]);
    srow[c4] = make_float4(ax, ay, az, aw);
    __syncthreads();

    float* obase = out + (size_t)n * C_ * NBIN + ph * PW_;
    #pragma unroll 4
    for (int i = tid; i < C_ * PW_; i += 448) {
        int c  = i / PW_;
        int p2 = i - c * PW_;
        obase[c * NBIN + p2] = s_out[p2][c];
    }
}

extern "C" void kernel_launch(void* const* d_in, const int* in_sizes, int n_in,
                              void* d_out, int out_size) {
    const float* feat = (const float*)d_in[0];
    const float* rois = (const float*)d_in[1];
    float*       out  = (float*)d_out;

    int N = in_sizes[1] / 5;

    dim3 tg(HW_ / 32, C_ / 32, B_);
    transpose_kernel<<<tg, dim3(32, 8)>>>(feat);

    dim3 mg(N, PH_);
    roialign_nhwc<<<mg, 448>>>(rois, out, N);
}